// round 5
// baseline (speedup 1.0000x reference)
#include <cuda_runtime.h>
#include <cstdint>

#define CH 64
#define N_MAX 100000
#define NF_MAX 400000

// Scratch (allocation-free rule: __device__ globals)
__device__ float g_agg[(size_t)N_MAX * CH];
__device__ float g_h1[(size_t)N_MAX * CH];
__device__ float g_h2[(size_t)N_MAX * CH];
__device__ int   g_is64;   // 1 if index arrays are int64, 0 if int32

// ---------------------------------------------------------------------------
// dtype detect: int64 indices (values < 2^31) viewed as int32 have every odd
// (high-word) slot == 0. 64 consecutive zero odd-slots in genuine int32 index
// data is probability ~0.
// ---------------------------------------------------------------------------
__global__ void detect_kernel(const int* __restrict__ ei32) {
    int is64 = 1;
    for (int i = 0; i < 64; i++) {
        if (ei32[2 * i + 1] != 0) { is64 = 0; break; }
    }
    g_is64 = is64;
}

__device__ __forceinline__ int load_idx(const void* p, long long i, int is64) {
    if (is64) return (int)((const long long*)p)[i];
    return ((const int*)p)[i];
}

// ---------------------------------------------------------------------------
// zero-fill
// ---------------------------------------------------------------------------
__global__ void zero_kernel(float4* __restrict__ p, int n4) {
    int i = blockIdx.x * blockDim.x + threadIdx.x;
    if (i < n4) p[i] = make_float4(0.f, 0.f, 0.f, 0.f);
}

// ---------------------------------------------------------------------------
// gather-scale-scatter: agg[dst] += x[src] * w   (16 threads per edge,
// each thread handles one float4 chunk of the 64-channel row; atomic side
// uses vectorized red.global.add.v4.f32, sm_90+)
// Indices are clamped into range: a wrong layout assumption then shows up as
// rel_err (diagnosable) instead of an illegal access (opaque).
// ---------------------------------------------------------------------------
__global__ void __launch_bounds__(256)
scatter_kernel(const float* __restrict__ x,
               const void* __restrict__ src_arr,
               const void* __restrict__ dst_arr,
               long long src_off, long long dst_off,
               const float* __restrict__ w,
               float* __restrict__ agg,
               int E, int n_src_rows, int n_dst_rows)
{
    int t = blockIdx.x * 256 + threadIdx.x;
    int e = t >> 4;
    if (e >= E) return;
    int c4 = t & 15;
    int is64 = g_is64;

    int src = load_idx(src_arr, (long long)e + src_off, is64);
    int dst = load_idx(dst_arr, (long long)e + dst_off, is64);
    src = min(max(src, 0), n_src_rows - 1);
    dst = min(max(dst, 0), n_dst_rows - 1);
    float wv = __ldg(&w[e]);

    float4 v = *(const float4*)(x + (size_t)src * CH + c4 * 4);
    v.x *= wv; v.y *= wv; v.z *= wv; v.w *= wv;

    float* p = agg + (size_t)dst * CH + c4 * 4;
    asm volatile("red.global.add.v4.f32 [%0], {%1, %2, %3, %4};"
                 :: "l"(p), "f"(v.x), "f"(v.y), "f"(v.z), "f"(v.w)
                 : "memory");
}

// ---------------------------------------------------------------------------
// combine: out[i,:] = agg[i,:] @ Wn + x[i,:] @ Wr + b
// 256 threads/block; 16 rows per block; thread (r = tid>>4, c4 = tid&15)
// produces out[row0+r][c4*4 .. c4*4+3]. Both 64x64 W matrices staged in smem.
// ---------------------------------------------------------------------------
__global__ void __launch_bounds__(256)
combine_kernel(const float* __restrict__ agg,
               const float* __restrict__ x,
               const float* __restrict__ Wn,
               const float* __restrict__ Wr,
               const float* __restrict__ b,
               float* __restrict__ out,
               int N)
{
    __shared__ float sWn[CH * CH];
    __shared__ float sWr[CH * CH];
    __shared__ float sA[16][CH + 4];
    __shared__ float sX[16][CH + 4];

    for (int i = threadIdx.x; i < CH * CH; i += 256) {
        sWn[i] = Wn[i];
        sWr[i] = Wr[i];
    }

    int r  = threadIdx.x >> 4;
    int c4 = threadIdx.x & 15;
    int row = blockIdx.x * 16 + r;

    if (row < N) {
        float4 a4 = *(const float4*)(agg + (size_t)row * CH + c4 * 4);
        float4 x4 = *(const float4*)(x   + (size_t)row * CH + c4 * 4);
        sA[r][c4 * 4 + 0] = a4.x; sA[r][c4 * 4 + 1] = a4.y;
        sA[r][c4 * 4 + 2] = a4.z; sA[r][c4 * 4 + 3] = a4.w;
        sX[r][c4 * 4 + 0] = x4.x; sX[r][c4 * 4 + 1] = x4.y;
        sX[r][c4 * 4 + 2] = x4.z; sX[r][c4 * 4 + 3] = x4.w;
    }
    __syncthreads();

    float4 bb = *(const float4*)(b + c4 * 4);
    float4 acc = bb;

#pragma unroll
    for (int k = 0; k < CH; k++) {
        float a  = sA[r][k];
        float xv = sX[r][k];
        float4 wn4 = *(const float4*)&sWn[k * CH + c4 * 4];
        float4 wr4 = *(const float4*)&sWr[k * CH + c4 * 4];
        acc.x += a * wn4.x + xv * wr4.x;
        acc.y += a * wn4.y + xv * wr4.y;
        acc.z += a * wn4.z + xv * wr4.z;
        acc.w += a * wn4.w + xv * wr4.w;
    }

    if (row < N)
        *(float4*)(out + (size_t)row * CH + c4 * 4) = acc;
}

// ---------------------------------------------------------------------------
// launch
// ---------------------------------------------------------------------------
extern "C" void kernel_launch(void* const* d_in, const int* in_sizes, int n_in,
                              void* d_out, int out_size)
{
    float *agg, *h1, *h2;
    cudaGetSymbolAddress((void**)&agg, g_agg);
    cudaGetSymbolAddress((void**)&h1,  g_h1);
    cudaGetSymbolAddress((void**)&h2,  g_h2);

    const float* x    = (const float*)d_in[0];
    const void*  ei   = d_in[1];          // [2, E] indices (dtype detected)
    const float* ea   = (const float*)d_in[2];
    const void*  psrc = d_in[3];
    const void*  pdst = d_in[4];
    const float* pw   = (const float*)d_in[5];

    // weights are always the LAST 6 inputs (n_fine scalar may or may not be
    // materialized as a device input)
    int wbase = n_in - 6;
    const float* Wr1 = (const float*)d_in[wbase + 0];
    const float* Wn1 = (const float*)d_in[wbase + 1];
    const float* b1  = (const float*)d_in[wbase + 2];
    const float* Wr2 = (const float*)d_in[wbase + 3];
    const float* Wn2 = (const float*)d_in[wbase + 4];
    const float* b2  = (const float*)d_in[wbase + 5];

    int N  = in_sizes[0] / CH;
    int E  = in_sizes[2];
    int EP = in_sizes[5];
    int NF = out_size / CH;

    float* out = (float*)d_out;

    int agg4 = N * (CH / 4);
    int out4 = NF * (CH / 4);
    int zb_agg = (agg4 + 255) / 256;
    int zb_out = (out4 + 255) / 256;
    int sc_blocks = (int)(((long long)E * 16 + 255) / 256);
    int sp_blocks = (int)(((long long)EP * 16 + 255) / 256);
    int cb_blocks = (N + 15) / 16;

    detect_kernel<<<1, 1>>>((const int*)ei);

    // ----- layer 1 -----
    zero_kernel<<<zb_agg, 256>>>((float4*)agg, agg4);
    scatter_kernel<<<sc_blocks, 256>>>(x, ei, ei, 0, E, ea, agg, E, N, N);
    combine_kernel<<<cb_blocks, 256>>>(agg, x, Wn1, Wr1, b1, h1, N);

    // ----- layer 2 -----
    zero_kernel<<<zb_agg, 256>>>((float4*)agg, agg4);
    scatter_kernel<<<sc_blocks, 256>>>(h1, ei, ei, 0, E, ea, agg, E, N, N);
    combine_kernel<<<cb_blocks, 256>>>(agg, h1, Wn2, Wr2, b2, h2, N);

    // ----- unpool -----
    zero_kernel<<<zb_out, 256>>>((float4*)out, out4);
    scatter_kernel<<<sp_blocks, 256>>>(h2, psrc, pdst, 0, 0, pw, out, EP, N, NF);
}

// round 7
// speedup vs baseline: 1.5239x; 1.5239x over previous
#include <cuda_runtime.h>
#include <cstdint>

#define CH 64
#define N_MAX 100000
#define NF_MAX 400000
#define E_MAX 1200000

// Scratch (allocation-free rule: __device__ globals)
__device__ float g_agg[(size_t)N_MAX * CH];
__device__ float g_h1[(size_t)N_MAX * CH];
__device__ float g_h2[(size_t)N_MAX * CH];
__device__ int   g_off_conv[N_MAX + 1];
__device__ int   g_off_pool[NF_MAX + 1];
__device__ int   g_cur[NF_MAX];
__device__ int   g_esrc_conv[E_MAX];
__device__ float g_ew_conv[E_MAX];
__device__ int   g_esrc_pool[E_MAX];
__device__ float g_ew_pool[E_MAX];
__device__ int   g_bsum[1024];
__device__ int   g_is64;

// ---------------------------------------------------------------------------
// dtype detect: int64 indices (values < 2^31) viewed as int32 have every odd
// (high-word) slot == 0.
// ---------------------------------------------------------------------------
__global__ void detect_kernel(const int* __restrict__ ei32) {
    int is64 = 1;
    for (int i = 0; i < 64; i++) {
        if (ei32[2 * i + 1] != 0) { is64 = 0; break; }
    }
    g_is64 = is64;
}

__device__ __forceinline__ int load_idx(const void* p, long long i, int is64) {
    if (is64) return (int)((const long long*)p)[i];
    return ((const int*)p)[i];
}

// ---------------------------------------------------------------------------
// CSR build: zero -> count -> scan(3 kernels) -> fill
// ---------------------------------------------------------------------------
__global__ void zero_int_kernel(int* __restrict__ p, int n) {
    int i = blockIdx.x * blockDim.x + threadIdx.x;
    if (i < n) p[i] = 0;
}

__global__ void count_kernel(const void* __restrict__ dst_arr, long long dst_off,
                             int* __restrict__ cnt, int E, int n_dst) {
    int e = blockIdx.x * blockDim.x + threadIdx.x;
    if (e >= E) return;
    int dst = load_idx(dst_arr, (long long)e + dst_off, g_is64);
    dst = min(max(dst, 0), n_dst - 1);
    atomicAdd(&cnt[dst + 1], 1);
}

// inclusive scan, 1024 elems/block; counts stored at idx+1 so inclusive scan
// yields exclusive offsets directly
__global__ void scan_block_kernel(int* __restrict__ data, int n, int* __restrict__ bsum) {
    __shared__ int s[1024];
    int i = blockIdx.x * 1024 + threadIdx.x;
    int v = (i < n) ? data[i] : 0;
    s[threadIdx.x] = v;
    __syncthreads();
#pragma unroll
    for (int d = 1; d < 1024; d <<= 1) {
        int t = (threadIdx.x >= d) ? s[threadIdx.x - d] : 0;
        __syncthreads();
        s[threadIdx.x] += t;
        __syncthreads();
    }
    if (i < n) data[i] = s[threadIdx.x];
    if (threadIdx.x == 1023) bsum[blockIdx.x] = s[1023];
}

__global__ void scan_mid_kernel(int* __restrict__ bsum, int nb) {
    __shared__ int s[1024];
    int i = threadIdx.x;
    s[i] = (i < nb) ? bsum[i] : 0;
    __syncthreads();
#pragma unroll
    for (int d = 1; d < 1024; d <<= 1) {
        int t = (i >= d) ? s[i - d] : 0;
        __syncthreads();
        s[i] += t;
        __syncthreads();
    }
    if (i < nb) bsum[i] = s[i];
}

__global__ void scan_add_kernel(int* __restrict__ data, int n, const int* __restrict__ bsum) {
    if (blockIdx.x == 0) return;
    int i = blockIdx.x * 1024 + threadIdx.x;
    if (i < n) data[i] += bsum[blockIdx.x - 1];
}

__global__ void fill_kernel(const void* __restrict__ src_arr, const void* __restrict__ dst_arr,
                            long long src_off, long long dst_off,
                            const float* __restrict__ w,
                            const int* __restrict__ off, int* __restrict__ cur,
                            int* __restrict__ esrc, float* __restrict__ ew,
                            int E, int n_src, int n_dst) {
    int e = blockIdx.x * blockDim.x + threadIdx.x;
    if (e >= E) return;
    int is64 = g_is64;
    int src = load_idx(src_arr, (long long)e + src_off, is64);
    int dst = load_idx(dst_arr, (long long)e + dst_off, is64);
    src = min(max(src, 0), n_src - 1);
    dst = min(max(dst, 0), n_dst - 1);
    int pos = off[dst] + atomicAdd(&cur[dst], 1);
    esrc[pos] = src;
    ew[pos] = w[e];
}

// ---------------------------------------------------------------------------
// CSR aggregate: out[dst,:] = sum_{edges->dst} w * x[src,:]
// 16 threads per dst row, each owns one float4 chunk. No atomics; every dst
// row written exactly once (zero-fill not needed).
// ---------------------------------------------------------------------------
__global__ void __launch_bounds__(256)
agg_kernel(const float* __restrict__ x,
           const int* __restrict__ off,
           const int* __restrict__ esrc,
           const float* __restrict__ ew,
           float* __restrict__ outv,
           int Nd)
{
    int t = blockIdx.x * 256 + threadIdx.x;
    int dst = t >> 4;
    if (dst >= Nd) return;
    int c4 = t & 15;

    int s = off[dst], e = off[dst + 1];
    float4 acc = make_float4(0.f, 0.f, 0.f, 0.f);
    for (int i = s; i < e; i++) {
        int   sr = __ldg(&esrc[i]);
        float wv = __ldg(&ew[i]);
        float4 v = *(const float4*)(x + (size_t)sr * CH + c4 * 4);
        acc.x += wv * v.x; acc.y += wv * v.y;
        acc.z += wv * v.z; acc.w += wv * v.w;
    }
    *(float4*)(outv + (size_t)dst * CH + c4 * 4) = acc;
}

// ---------------------------------------------------------------------------
// combine: out[i,:] = agg[i,:] @ Wn + x[i,:] @ Wr + b
// 512 threads, 64 rows/block, 2 rows per thread (W smem reads amortized 2x
// and broadcast-merged within each warp). Dynamic smem 67584B.
// ---------------------------------------------------------------------------
#define AROW 68   // padded row stride for sA/sX

__global__ void __launch_bounds__(512)
combine_kernel(const float* __restrict__ agg,
               const float* __restrict__ x,
               const float* __restrict__ Wn,
               const float* __restrict__ Wr,
               const float* __restrict__ b,
               float* __restrict__ out,
               int N)
{
    extern __shared__ float sm[];
    float* sWn = sm;                       // 4096
    float* sWr = sm + 4096;                // 4096
    float* sA  = sm + 8192;                // 64*AROW
    float* sX  = sm + 8192 + 64 * AROW;    // 64*AROW

    int tid = threadIdx.x;
    for (int i = tid; i < CH * CH; i += 512) {
        sWn[i] = Wn[i];
        sWr[i] = Wr[i];
    }

    int rs = tid >> 4;       // 0..31
    int c4 = tid & 15;
    int r0 = rs * 2;
    int row0 = blockIdx.x * 64 + r0;

#pragma unroll
    for (int rr = 0; rr < 2; rr++) {
        int row = row0 + rr;
        float4 a4 = make_float4(0.f, 0.f, 0.f, 0.f);
        float4 x4 = make_float4(0.f, 0.f, 0.f, 0.f);
        if (row < N) {
            a4 = *(const float4*)(agg + (size_t)row * CH + c4 * 4);
            x4 = *(const float4*)(x   + (size_t)row * CH + c4 * 4);
        }
        int base = (r0 + rr) * AROW + c4 * 4;
        sA[base + 0] = a4.x; sA[base + 1] = a4.y; sA[base + 2] = a4.z; sA[base + 3] = a4.w;
        sX[base + 0] = x4.x; sX[base + 1] = x4.y; sX[base + 2] = x4.z; sX[base + 3] = x4.w;
    }
    __syncthreads();

    float4 bb = *(const float4*)(b + c4 * 4);
    float4 acc0 = bb, acc1 = bb;

#pragma unroll 8
    for (int k = 0; k < CH; k++) {
        float4 wn = *(const float4*)&sWn[k * CH + c4 * 4];
        float4 wr = *(const float4*)&sWr[k * CH + c4 * 4];
        float a0 = sA[r0 * AROW + k];
        float a1 = sA[(r0 + 1) * AROW + k];
        float x0 = sX[r0 * AROW + k];
        float x1 = sX[(r0 + 1) * AROW + k];
        acc0.x += a0 * wn.x + x0 * wr.x;
        acc0.y += a0 * wn.y + x0 * wr.y;
        acc0.z += a0 * wn.z + x0 * wr.z;
        acc0.w += a0 * wn.w + x0 * wr.w;
        acc1.x += a1 * wn.x + x1 * wr.x;
        acc1.y += a1 * wn.y + x1 * wr.y;
        acc1.z += a1 * wn.z + x1 * wr.z;
        acc1.w += a1 * wn.w + x1 * wr.w;
    }

    if (row0 < N)
        *(float4*)(out + (size_t)row0 * CH + c4 * 4) = acc0;
    if (row0 + 1 < N)
        *(float4*)(out + (size_t)(row0 + 1) * CH + c4 * 4) = acc1;
}

#define COMBINE_SMEM ((4096 * 2 + 64 * AROW * 2) * 4)

// ---------------------------------------------------------------------------
// helpers for CSR pipeline
// ---------------------------------------------------------------------------
static void build_csr(const void* src_arr, const void* dst_arr,
                      long long src_off, long long dst_off,
                      const float* w, int E, int n_src, int n_dst,
                      int* off, int* cur, int* esrc, float* ew)
{
    int n1 = n_dst + 1;
    int zb = (n1 + 255) / 256;
    zero_int_kernel<<<zb, 256>>>(off, n1);
    zero_int_kernel<<<(n_dst + 255) / 256, 256>>>(cur, n_dst);
    count_kernel<<<(E + 255) / 256, 256>>>(dst_arr, dst_off, off, E, n_dst);
    int nb = (n1 + 1023) / 1024;
    int* bsum;
    cudaGetSymbolAddress((void**)&bsum, g_bsum);
    scan_block_kernel<<<nb, 1024>>>(off, n1, bsum);
    scan_mid_kernel<<<1, 1024>>>(bsum, nb);
    scan_add_kernel<<<nb, 1024>>>(off, n1, bsum);
    fill_kernel<<<(E + 255) / 256, 256>>>(src_arr, dst_arr, src_off, dst_off,
                                          w, off, cur, esrc, ew, E, n_src, n_dst);
}

// ---------------------------------------------------------------------------
// launch
// ---------------------------------------------------------------------------
extern "C" void kernel_launch(void* const* d_in, const int* in_sizes, int n_in,
                              void* d_out, int out_size)
{
    float *agg, *h1, *h2, *ewc, *ewp;
    int *offc, *offp, *cur, *esc, *esp;
    cudaGetSymbolAddress((void**)&agg,  g_agg);
    cudaGetSymbolAddress((void**)&h1,   g_h1);
    cudaGetSymbolAddress((void**)&h2,   g_h2);
    cudaGetSymbolAddress((void**)&offc, g_off_conv);
    cudaGetSymbolAddress((void**)&offp, g_off_pool);
    cudaGetSymbolAddress((void**)&cur,  g_cur);
    cudaGetSymbolAddress((void**)&esc,  g_esrc_conv);
    cudaGetSymbolAddress((void**)&ewc,  g_ew_conv);
    cudaGetSymbolAddress((void**)&esp,  g_esrc_pool);
    cudaGetSymbolAddress((void**)&ewp,  g_ew_pool);

    cudaFuncSetAttribute(combine_kernel,
                         cudaFuncAttributeMaxDynamicSharedMemorySize, COMBINE_SMEM);

    const float* x    = (const float*)d_in[0];
    const void*  ei   = d_in[1];          // [2, E] indices (dtype detected)
    const float* ea   = (const float*)d_in[2];
    const void*  psrc = d_in[3];
    const void*  pdst = d_in[4];
    const float* pw   = (const float*)d_in[5];

    int wbase = n_in - 6;   // weights are always the last 6 inputs
    const float* Wr1 = (const float*)d_in[wbase + 0];
    const float* Wn1 = (const float*)d_in[wbase + 1];
    const float* b1  = (const float*)d_in[wbase + 2];
    const float* Wr2 = (const float*)d_in[wbase + 3];
    const float* Wn2 = (const float*)d_in[wbase + 4];
    const float* b2  = (const float*)d_in[wbase + 5];

    int N  = in_sizes[0] / CH;
    int E  = in_sizes[2];
    int EP = in_sizes[5];
    int NF = out_size / CH;

    float* out = (float*)d_out;

    int ab_conv = (N * 16 + 255) / 256;
    int ab_pool = (NF * 16 + 255) / 256;
    int cb = (N + 63) / 64;

    detect_kernel<<<1, 1>>>((const int*)ei);

    // CSR for conv graph (reused by both layers) and pool graph
    build_csr(ei, ei, 0, E, ea, E, N, N, offc, cur, esc, ewc);
    build_csr(psrc, pdst, 0, 0, pw, EP, N, NF, offp, cur, esp, ewp);

    // ----- layer 1 -----
    agg_kernel<<<ab_conv, 256>>>(x, offc, esc, ewc, agg, N);
    combine_kernel<<<cb, 512, COMBINE_SMEM>>>(agg, x, Wn1, Wr1, b1, h1, N);

    // ----- layer 2 -----
    agg_kernel<<<ab_conv, 256>>>(h1, offc, esc, ewc, agg, N);
    combine_kernel<<<cb, 512, COMBINE_SMEM>>>(agg, h1, Wn2, Wr2, b2, h2, N);

    // ----- unpool (writes every output row; no zero-fill needed) -----
    agg_kernel<<<ab_pool, 256>>>(h2, offp, esp, ewp, out, NF);
}